// round 1
// baseline (speedup 1.0000x reference)
#include <cuda_runtime.h>
#include <cstdint>

#define DEV_INLINE __device__ __forceinline__

constexpr int N  = 256;
constexpr int T  = 1024;
constexpr int P  = 4;
constexpr int AS = T + P;        // alpha row stride = 1028
constexpr int Tp = T - P;        // 1020

// ---- btl tiling ----
constexpr int TI     = 8;                       // i-rows per tile
constexpr int NTILE  = N / TI;                  // 32
constexpr int TPAIRS = NTILE * (NTILE + 1) / 2; // 528 tile pairs (jt >= it)
constexpr int TT     = 256;                     // t per block
constexpr int NTT    = T / TT;                  // 4
constexpr int BTL_BLOCKS = TPAIRS * NTT;        // 2112

// ---- ar tiling ----
constexpr int AR_TT     = 8;
constexpr int AR_BLOCKS = (Tp + AR_TT - 1) / AR_TT; // 128

constexpr int TOTAL_BLOCKS = BTL_BLOCKS + AR_BLOCKS; // 2240

__device__ double g_btl_partial[BTL_BLOCKS];
__device__ double g_ar_partial[AR_BLOCKS];
__device__ float  g_phiT[P * N * N];  // PhiT[k][m][n]

struct SmemBTL {
    float si[TI][TT];
    float ei[TI][TT];
    float sj[TI][TT];
    float ej[TI][TT];
    float red[8];
};
struct SmemAR {
    float sa[N][AR_TT + P];   // alpha[m, t0 + c], c in [0, 12)
    float red[8];
};
union SmemU { SmemBTL b; SmemAR a; };

DEV_INLINE float warpReduce(float v) {
    #pragma unroll
    for (int o = 16; o > 0; o >>= 1)
        v += __shfl_xor_sync(0xffffffffu, v, o);
    return v;
}

// returns full sum in thread 0 (other threads: undefined)
DEV_INLINE float blockReduce(float v, float* red) {
    v = warpReduce(v);
    if ((threadIdx.x & 31) == 0) red[threadIdx.x >> 5] = v;
    __syncthreads();
    float r = 0.f;
    if (threadIdx.x < 32) {
        r = (threadIdx.x < 8) ? red[threadIdx.x] : 0.f;
        #pragma unroll
        for (int o = 4; o > 0; o >>= 1)
            r += __shfl_xor_sync(0xffffffffu, r, o);
    }
    __syncthreads();   // red reusable after return
    return r;
}

// ---------------- BTL part ----------------
DEV_INLINE void btl_block(const float* __restrict__ Z,
                          const float* __restrict__ W,
                          const float* __restrict__ alpha,
                          SmemBTL& s, int bid) {
    const int ttile = bid & (NTT - 1);
    int tp = bid >> 2;  // NTT == 4
    // map linear tile-pair -> (it, jt), jt >= it
    int it = 0;
    #pragma unroll 1
    while (tp >= NTILE - it) { tp -= NTILE - it; ++it; }
    const int jt = it + tp;

    const int i0 = it * TI, j0 = jt * TI;
    const int t0 = ttile * TT;
    const int tid = threadIdx.x;

    // stage s and exp(s) rows for both tiles
    #pragma unroll
    for (int r = 0; r < TI; ++r) {
        float vi = alpha[(i0 + r) * AS + P + t0 + tid];
        s.si[r][tid] = vi;
        s.ei[r][tid] = __expf(vi);
        float vj = alpha[(j0 + r) * AS + P + t0 + tid];
        s.sj[r][tid] = vj;
        s.ej[r][tid] = __expf(vj);
    }
    __syncthreads();

    const bool diag = (it == jt);
    float acc = 0.f;

    #pragma unroll
    for (int pi = 0; pi < TI; ++pi) {
        const float a  = s.si[pi][tid];
        const float ea = s.ei[pi][tid];
        const size_t rowbase = ((size_t)(i0 + pi) * N + j0) * T + t0 + tid;
        const float* zr = Z + rowbase;
        const float* wr = W + rowbase;
        #pragma unroll
        for (int pj = 0; pj < TI; ++pj) {
            if (diag && pj <= pi) continue;   // upper triangle only
            float z = zr[(size_t)pj * T];
            float w = wr[(size_t)pj * T];
            float b  = s.sj[pj][tid];
            float eb = s.ej[pj][tid];
            float lse = __logf(ea + eb);
            acc += z * a + w * b - (z + w) * lse;
        }
    }

    float tot = blockReduce(acc, s.red);
    if (tid == 0) g_btl_partial[bid] = (double)tot;
}

// ---------------- AR part ----------------
DEV_INLINE void ar_block(const float* __restrict__ alpha,
                         SmemAR& s, int abid) {
    const int t0  = abid * AR_TT;
    const int tid = threadIdx.x;   // = n

    // alpha tile: rows m = 0..255, cols t0 .. t0+11 (max col 1027 < 1028)
    #pragma unroll
    for (int c = 0; c < AR_TT + P; ++c)
        s.sa[tid][c] = alpha[tid * AS + t0 + c];
    __syncthreads();

    float acc[AR_TT];
    #pragma unroll
    for (int tt = 0; tt < AR_TT; ++tt) acc[tt] = 0.f;

    #pragma unroll 2
    for (int m = 0; m < N; ++m) {
        float av[AR_TT + P];
        #pragma unroll
        for (int c = 0; c < AR_TT + P; ++c) av[c] = s.sa[m][c];
        #pragma unroll
        for (int k = 0; k < P; ++k) {
            float phi = g_phiT[((k * N) + m) * N + tid]; // coalesced over tid
            #pragma unroll
            for (int tt = 0; tt < AR_TT; ++tt)
                acc[tt] = fmaf(phi, av[k + tt], acc[tt]);
        }
    }

    // ar_err contribution via: sum_{n,n2} (S_n - A_n2)^2
    //   = N*sum S^2 - 2*(sum S)(sum A) + N*sum A^2   (per t)
    double part = 0.0;
    #pragma unroll 1
    for (int tt = 0; tt < AR_TT; ++tt) {
        float S = acc[tt];
        float A = s.sa[tid][tt + P];        // actual[n, t0+tt] = alpha[n, t0+tt+P]
        float s1 = blockReduce(S, s.red);
        float s2 = blockReduce(S * S, s.red);
        float a1 = blockReduce(A, s.red);
        float a2 = blockReduce(A * A, s.red);
        if (tid == 0 && (t0 + tt) < Tp) {
            part += (double)N * (double)s2
                  - 2.0 * (double)s1 * (double)a1
                  + (double)N * (double)a2;
        }
    }
    if (tid == 0) g_ar_partial[abid] = part;
}

// ---------------- kernels ----------------
__global__ void phiT_kernel(const float* __restrict__ Phi) {
    int idx = blockIdx.x * 256 + threadIdx.x;   // 0 .. 262143
    int k = idx >> 16;
    int r = idx & 0xFFFF;
    int n = r >> 8;
    int m = r & 0xFF;
    g_phiT[(k << 16) + (m << 8) + n] = Phi[idx];
}

__global__ __launch_bounds__(256) void mega_kernel(const float* __restrict__ Z,
                                                   const float* __restrict__ W,
                                                   const float* __restrict__ alpha) {
    __shared__ SmemU sm;
    int bid = blockIdx.x;
    if (bid < BTL_BLOCKS) btl_block(Z, W, alpha, sm.b, bid);
    else                  ar_block(alpha, sm.a, bid - BTL_BLOCKS);
}

__global__ void finalize_kernel(float* __restrict__ out) {
    __shared__ double sd[256];
    const int tid = threadIdx.x;

    double s = 0.0;
    for (int i = tid; i < BTL_BLOCKS; i += 256) s += g_btl_partial[i];
    sd[tid] = s;
    __syncthreads();
    #pragma unroll
    for (int o = 128; o > 0; o >>= 1) {
        if (tid < o) sd[tid] += sd[tid + o];
        __syncthreads();
    }
    if (tid == 0) out[0] = (float)sd[0];
    __syncthreads();

    s = 0.0;
    for (int i = tid; i < AR_BLOCKS; i += 256) s += g_ar_partial[i];
    sd[tid] = s;
    __syncthreads();
    #pragma unroll
    for (int o = 128; o > 0; o >>= 1) {
        if (tid < o) sd[tid] += sd[tid + o];
        __syncthreads();
    }
    if (tid == 0) out[1] = (float)sd[0];
}

extern "C" void kernel_launch(void* const* d_in, const int* in_sizes, int n_in,
                              void* d_out, int out_size) {
    const float* Z     = (const float*)d_in[0];
    const float* W     = (const float*)d_in[1];
    const float* Phi   = (const float*)d_in[2];
    const float* alpha = (const float*)d_in[3];
    float* out = (float*)d_out;

    phiT_kernel<<<(P * N * N) / 256, 256>>>(Phi);
    mega_kernel<<<TOTAL_BLOCKS, 256>>>(Z, W, alpha);
    finalize_kernel<<<1, 256>>>(out);
}

// round 3
// speedup vs baseline: 1.4325x; 1.4325x over previous
#include <cuda_runtime.h>
#include <cstdint>

#define DEV_INLINE __device__ __forceinline__

constexpr int N  = 256;
constexpr int T  = 1024;
constexpr int P  = 4;
constexpr int AS = T + P;        // alpha row stride = 1028
constexpr int Tp = T - P;        // 1020

// ---- btl tiling ----
constexpr int TI     = 8;                       // i-rows per tile
constexpr int NTILE  = N / TI;                  // 32
constexpr int TPAIRS = NTILE * (NTILE + 1) / 2; // 528 tile pairs (jt >= it)
constexpr int TT     = 256;                     // t per block
constexpr int NTT    = T / TT;                  // 4
constexpr int BTL_BLOCKS = TPAIRS * NTT;        // 2112

// ---- ar tiling ----
constexpr int AR_TT     = 8;
constexpr int AR_BLOCKS = (Tp + AR_TT - 1) / AR_TT; // 128

constexpr int TOTAL_BLOCKS = BTL_BLOCKS + AR_BLOCKS; // 2240

__device__ double g_btl_partial[BTL_BLOCKS];
__device__ double g_ar_partial[AR_BLOCKS];
__device__ float  g_phiT[P * N * N];  // PhiT[k][m][n]

struct SmemBTL {
    float red[8];
};
struct SmemAR {
    float sa[N][AR_TT + P];   // alpha[m, t0 + c], c in [0, 12)
    float red[8];
};
union SmemU { SmemBTL b; SmemAR a; };

DEV_INLINE float warpReduce(float v) {
    #pragma unroll
    for (int o = 16; o > 0; o >>= 1)
        v += __shfl_xor_sync(0xffffffffu, v, o);
    return v;
}

// returns full sum in thread 0 (other threads: undefined)
DEV_INLINE float blockReduce(float v, float* red) {
    v = warpReduce(v);
    if ((threadIdx.x & 31) == 0) red[threadIdx.x >> 5] = v;
    __syncthreads();
    float r = 0.f;
    if (threadIdx.x < 32) {
        r = (threadIdx.x < 8) ? red[threadIdx.x] : 0.f;
        #pragma unroll
        for (int o = 4; o > 0; o >>= 1)
            r += __shfl_xor_sync(0xffffffffu, r, o);
    }
    __syncthreads();   // red reusable after return
    return r;
}

// ---------------- BTL part (register-staged, no smem) ----------------
template<bool DIAG>
DEV_INLINE float btl_tile(const float* __restrict__ Z,
                          const float* __restrict__ W,
                          const float* __restrict__ alpha,
                          int i0, int j0, int t0) {
    const int tid = threadIdx.x;

    // Stage s and exp(s) for both row-tiles in registers (coalesced alpha reads)
    float si[TI], ei[TI], sj[TI], ej[TI];
    #pragma unroll
    for (int r = 0; r < TI; ++r) {
        si[r] = alpha[(i0 + r) * AS + P + t0 + tid];
        sj[r] = alpha[(j0 + r) * AS + P + t0 + tid];
    }
    #pragma unroll
    for (int r = 0; r < TI; ++r) {
        ei[r] = __expf(si[r]);
        ej[r] = __expf(sj[r]);
    }

    float acc0 = 0.f, acc1 = 0.f;
    const size_t base = ((size_t)i0 * N + j0) * T + t0 + tid;

    #pragma unroll
    for (int pi = 0; pi < TI; ++pi) {
        const float* zr = Z + base + (size_t)pi * N * T;
        const float* wr = W + base + (size_t)pi * N * T;

        // batched independent loads -> high MLP
        float z[TI], w[TI];
        #pragma unroll
        for (int pj = 0; pj < TI; ++pj)
            if (!DIAG || pj > pi) z[pj] = zr[(size_t)pj * T];
        #pragma unroll
        for (int pj = 0; pj < TI; ++pj)
            if (!DIAG || pj > pi) w[pj] = wr[(size_t)pj * T];

        #pragma unroll
        for (int pj = 0; pj < TI; ++pj) {
            if (!DIAG || pj > pi) {
                float lse = __logf(ei[pi] + ej[pj]);
                acc0 = fmaf(z[pj], si[pi] - lse, acc0);
                acc1 = fmaf(w[pj], sj[pj] - lse, acc1);
            }
        }
    }
    return acc0 + acc1;
}

DEV_INLINE void btl_block(const float* __restrict__ Z,
                          const float* __restrict__ W,
                          const float* __restrict__ alpha,
                          SmemBTL& s, int bid) {
    const int ttile = bid & (NTT - 1);
    int tp = bid >> 2;  // NTT == 4
    int it = 0;
    #pragma unroll 1
    while (tp >= NTILE - it) { tp -= NTILE - it; ++it; }
    const int jt = it + tp;

    const int i0 = it * TI, j0 = jt * TI;
    const int t0 = ttile * TT;

    float acc;
    if (it == jt) acc = btl_tile<true >(Z, W, alpha, i0, j0, t0);
    else          acc = btl_tile<false>(Z, W, alpha, i0, j0, t0);

    float tot = blockReduce(acc, s.red);
    if (threadIdx.x == 0) g_btl_partial[bid] = (double)tot;
}

// ---------------- AR part ----------------
DEV_INLINE void ar_block(const float* __restrict__ alpha,
                         SmemAR& s, int abid) {
    const int t0  = abid * AR_TT;
    const int tid = threadIdx.x;   // = n

    #pragma unroll
    for (int c = 0; c < AR_TT + P; ++c)
        s.sa[tid][c] = alpha[tid * AS + t0 + c];
    __syncthreads();

    float acc[AR_TT];
    #pragma unroll
    for (int tt = 0; tt < AR_TT; ++tt) acc[tt] = 0.f;

    #pragma unroll 2
    for (int m = 0; m < N; ++m) {
        float av[AR_TT + P];
        #pragma unroll
        for (int c = 0; c < AR_TT + P; ++c) av[c] = s.sa[m][c];
        #pragma unroll
        for (int k = 0; k < P; ++k) {
            float phi = g_phiT[((k * N) + m) * N + tid]; // coalesced over tid
            #pragma unroll
            for (int tt = 0; tt < AR_TT; ++tt)
                acc[tt] = fmaf(phi, av[k + tt], acc[tt]);
        }
    }

    // sum_{n,n2} (S_n - A_n2)^2 = N*sum S^2 - 2*(sum S)(sum A) + N*sum A^2
    double part = 0.0;
    #pragma unroll 1
    for (int tt = 0; tt < AR_TT; ++tt) {
        float S = acc[tt];
        float A = s.sa[tid][tt + P];
        float s1 = blockReduce(S, s.red);
        float s2 = blockReduce(S * S, s.red);
        float a1 = blockReduce(A, s.red);
        float a2 = blockReduce(A * A, s.red);
        if (tid == 0 && (t0 + tt) < Tp) {
            part += (double)N * (double)s2
                  - 2.0 * (double)s1 * (double)a1
                  + (double)N * (double)a2;
        }
    }
    if (tid == 0) g_ar_partial[abid] = part;
}

// ---------------- kernels ----------------
__global__ __launch_bounds__(256) void phiT_kernel(const float* __restrict__ Phi) {
    __shared__ float tile[32][33];
    const int k  = blockIdx.z;
    const int nb = blockIdx.y * 32;
    const int mb = blockIdx.x * 32;
    const int tx = threadIdx.x & 31;
    const int ty = threadIdx.x >> 5;           // 0..7

    const float* src = Phi + (k << 16);
    #pragma unroll
    for (int r = 0; r < 4; ++r)
        tile[ty + r * 8][tx] = src[(nb + ty + r * 8) * N + mb + tx];
    __syncthreads();

    float* dst = g_phiT + (k << 16);
    #pragma unroll
    for (int r = 0; r < 4; ++r)
        dst[(mb + ty + r * 8) * N + nb + tx] = tile[tx][ty + r * 8];
}

__global__ __launch_bounds__(256, 3) void mega_kernel(const float* __restrict__ Z,
                                                      const float* __restrict__ W,
                                                      const float* __restrict__ alpha) {
    __shared__ SmemU sm;
    int bid = blockIdx.x;
    // AR blocks FIRST: long FMA-bound CTAs start in wave 1 and overlap with
    // the memory-bound btl blocks instead of forming a serial tail.
    if (bid < AR_BLOCKS) ar_block(alpha, sm.a, bid);
    else                 btl_block(Z, W, alpha, sm.b, bid - AR_BLOCKS);
}

__global__ __launch_bounds__(256) void finalize_kernel(float* __restrict__ out) {
    __shared__ double sd[256];
    const int tid = threadIdx.x;

    double s = 0.0;
    for (int i = tid; i < BTL_BLOCKS; i += 256) s += g_btl_partial[i];
    sd[tid] = s;
    __syncthreads();
    #pragma unroll
    for (int o = 128; o > 0; o >>= 1) {
        if (tid < o) sd[tid] += sd[tid + o];
        __syncthreads();
    }
    if (tid == 0) out[0] = (float)sd[0];
    __syncthreads();

    s = 0.0;
    for (int i = tid; i < AR_BLOCKS; i += 256) s += g_ar_partial[i];
    sd[tid] = s;
    __syncthreads();
    #pragma unroll
    for (int o = 128; o > 0; o >>= 1) {
        if (tid < o) sd[tid] += sd[tid + o];
        __syncthreads();
    }
    if (tid == 0) out[1] = (float)sd[0];
}

extern "C" void kernel_launch(void* const* d_in, const int* in_sizes, int n_in,
                              void* d_out, int out_size) {
    const float* Z     = (const float*)d_in[0];
    const float* W     = (const float*)d_in[1];
    const float* Phi   = (const float*)d_in[2];
    const float* alpha = (const float*)d_in[3];
    float* out = (float*)d_out;

    phiT_kernel<<<dim3(8, 8, 4), 256>>>(Phi);
    mega_kernel<<<TOTAL_BLOCKS, 256>>>(Z, W, alpha);
    finalize_kernel<<<1, 256>>>(out);
}

// round 4
// speedup vs baseline: 1.4576x; 1.0175x over previous
#include <cuda_runtime.h>
#include <cstdint>

#define DEV_INLINE __device__ __forceinline__

constexpr int N  = 256;
constexpr int T  = 1024;
constexpr int P  = 4;
constexpr int AS = T + P;        // alpha row stride = 1028
constexpr int Tp = T - P;        // 1020

// ---- btl tiling: 8i x 8j x 64t per block, bulk-staged through smem ----
constexpr int TI     = 8;
constexpr int NTILE  = N / TI;                  // 32
constexpr int TPAIRS = NTILE * (NTILE + 1) / 2; // 528
constexpr int TT     = 64;                      // t per block
constexpr int NTT    = T / TT;                  // 16
constexpr int BTL_BLOCKS = TPAIRS * NTT;        // 8448

// ---- ar tiling ----
constexpr int AR_TT     = 8;
constexpr int AR_BLOCKS = (Tp + AR_TT - 1) / AR_TT; // 128

constexpr int TOTAL_BLOCKS = BTL_BLOCKS + AR_BLOCKS; // 8576

__device__ float  g_btl_partial[BTL_BLOCKS];
__device__ double g_ar_partial[AR_BLOCKS];
__device__ float  g_phiT[P * N * N];  // PhiT[k][m][n]

struct __align__(16) SmemBTL {
    float z[64][TT];    // 16 KB  (64 pairs x 64 t)
    float w[64][TT];    // 16 KB
    float ss[16][TT];   // 4 KB   rows 0..7 = s_i, rows 8..15 = s_j
    float es[16][TT];   // 4 KB   exp of ss
    float red[8];
};
struct SmemAR {
    float sa[N][AR_TT + P];
    float red[8];
};
union SmemU { SmemBTL b; SmemAR a; };

DEV_INLINE float warpReduce(float v) {
    #pragma unroll
    for (int o = 16; o > 0; o >>= 1)
        v += __shfl_xor_sync(0xffffffffu, v, o);
    return v;
}

DEV_INLINE float blockReduce(float v, float* red) {
    v = warpReduce(v);
    if ((threadIdx.x & 31) == 0) red[threadIdx.x >> 5] = v;
    __syncthreads();
    float r = 0.f;
    if (threadIdx.x < 32) {
        r = (threadIdx.x < 8) ? red[threadIdx.x] : 0.f;
        #pragma unroll
        for (int o = 4; o > 0; o >>= 1)
            r += __shfl_xor_sync(0xffffffffu, r, o);
    }
    __syncthreads();
    return r;
}

// ---------------- BTL part: bulk-load phase + compute phase ----------------
template<bool DIAG>
DEV_INLINE float btl_compute(SmemBTL& s, int h, int lane) {
    float acc0 = 0.f, acc1 = 0.f;
    #pragma unroll
    for (int pp = 0; pp < 16; ++pp) {
        const int p  = h * 16 + pp;     // warp-uniform
        const int pi = p >> 3;
        const int pj = p & 7;
        if (DIAG && pj <= pi) continue; // warp-uniform branch (h uniform per warp)
        float z = s.z[p][lane];
        float w = s.w[p][lane];
        float a = s.ss[pi][lane];
        float b = s.ss[8 + pj][lane];
        float lse = __logf(s.es[pi][lane] + s.es[8 + pj][lane]);
        acc0 = fmaf(z, a - lse, acc0);
        acc1 = fmaf(w, b - lse, acc1);
    }
    return acc0 + acc1;
}

DEV_INLINE void btl_block(const float* __restrict__ Z,
                          const float* __restrict__ W,
                          const float* __restrict__ alpha,
                          SmemBTL& s, int bid) {
    const int ttile = bid & (NTT - 1);
    int tp = bid >> 4;                  // NTT == 16
    int it = 0;
    #pragma unroll 1
    while (tp >= NTILE - it) { tp -= NTILE - it; ++it; }
    const int jt = it + tp;

    const int i0 = it * TI, j0 = jt * TI;
    const int t0 = ttile * TT;
    const int tid = threadIdx.x;

    // ---- load phase: fully independent loads, maximal MLP ----
    // alpha staging: 16 rows x 64 t = 1024 floats (coalesced)
    float* ssf = &s.ss[0][0];
    float* esf = &s.es[0][0];
    #pragma unroll
    for (int itr = 0; itr < 4; ++itr) {
        int i2  = tid + 256 * itr;
        int row = i2 >> 6;              // 0..15
        int col = i2 & 63;
        int grow = (row < 8) ? (i0 + row) : (j0 + row - 8);
        float v = alpha[grow * AS + P + t0 + col];
        ssf[i2] = v;
        esf[i2] = __expf(v);
    }

    // Z/W tiles: 64 pairs x 64 t = 1024 float4 each; 8 independent LDG.128/thread
    const float4* Z4 = (const float4*)Z;
    const float4* W4 = (const float4*)W;
    float4* zb = (float4*)&s.z[0][0];
    float4* wb = (float4*)&s.w[0][0];
    #pragma unroll
    for (int itr = 0; itr < 4; ++itr) {
        int i2   = tid + 256 * itr;
        int prow = i2 >> 4;             // pair index 0..63
        int col4 = i2 & 15;
        int pi = prow >> 3, pj = prow & 7;
        size_t g = ((size_t)(i0 + pi) * N + (j0 + pj)) * (T / 4) + (t0 >> 2) + col4;
        zb[i2] = Z4[g];
        wb[i2] = W4[g];
    }
    __syncthreads();

    // ---- compute phase ----
    const int lane = tid & 63;
    const int h    = tid >> 6;          // warp-uniform
    float acc;
    if (it == jt) acc = btl_compute<true >(s, h, lane);
    else          acc = btl_compute<false>(s, h, lane);

    float tot = blockReduce(acc, s.red);
    if (tid == 0) g_btl_partial[bid] = tot;
}

// ---------------- AR part (unchanged, proven) ----------------
DEV_INLINE void ar_block(const float* __restrict__ alpha,
                         SmemAR& s, int abid) {
    const int t0  = abid * AR_TT;
    const int tid = threadIdx.x;   // = n

    #pragma unroll
    for (int c = 0; c < AR_TT + P; ++c)
        s.sa[tid][c] = alpha[tid * AS + t0 + c];
    __syncthreads();

    float acc[AR_TT];
    #pragma unroll
    for (int tt = 0; tt < AR_TT; ++tt) acc[tt] = 0.f;

    #pragma unroll 2
    for (int m = 0; m < N; ++m) {
        float av[AR_TT + P];
        #pragma unroll
        for (int c = 0; c < AR_TT + P; ++c) av[c] = s.sa[m][c];
        #pragma unroll
        for (int k = 0; k < P; ++k) {
            float phi = g_phiT[((k * N) + m) * N + tid]; // coalesced over tid
            #pragma unroll
            for (int tt = 0; tt < AR_TT; ++tt)
                acc[tt] = fmaf(phi, av[k + tt], acc[tt]);
        }
    }

    // sum_{n,n2} (S_n - A_n2)^2 = N*sum S^2 - 2*(sum S)(sum A) + N*sum A^2
    double part = 0.0;
    #pragma unroll 1
    for (int tt = 0; tt < AR_TT; ++tt) {
        float S = acc[tt];
        float A = s.sa[tid][tt + P];
        float s1 = blockReduce(S, s.red);
        float s2 = blockReduce(S * S, s.red);
        float a1 = blockReduce(A, s.red);
        float a2 = blockReduce(A * A, s.red);
        if (tid == 0 && (t0 + tt) < Tp) {
            part += (double)N * (double)s2
                  - 2.0 * (double)s1 * (double)a1
                  + (double)N * (double)a2;
        }
    }
    if (tid == 0) g_ar_partial[abid] = part;
}

// ---------------- kernels ----------------
__global__ __launch_bounds__(256) void phiT_kernel(const float* __restrict__ Phi) {
    __shared__ float tile[32][33];
    const int k  = blockIdx.z;
    const int nb = blockIdx.y * 32;
    const int mb = blockIdx.x * 32;
    const int tx = threadIdx.x & 31;
    const int ty = threadIdx.x >> 5;           // 0..7

    const float* src = Phi + (k << 16);
    #pragma unroll
    for (int r = 0; r < 4; ++r)
        tile[ty + r * 8][tx] = src[(nb + ty + r * 8) * N + mb + tx];
    __syncthreads();

    float* dst = g_phiT + (k << 16);
    #pragma unroll
    for (int r = 0; r < 4; ++r)
        dst[(mb + ty + r * 8) * N + nb + tx] = tile[tx][ty + r * 8];
}

__global__ __launch_bounds__(256, 4) void mega_kernel(const float* __restrict__ Z,
                                                      const float* __restrict__ W,
                                                      const float* __restrict__ alpha) {
    __shared__ SmemU sm;
    int bid = blockIdx.x;
    // AR blocks FIRST: long FMA-bound CTAs start in wave 1 and overlap with
    // the memory-bound btl blocks instead of forming a serial tail.
    if (bid < AR_BLOCKS) ar_block(alpha, sm.a, bid);
    else                 btl_block(Z, W, alpha, sm.b, bid - AR_BLOCKS);
}

__global__ __launch_bounds__(256) void finalize_kernel(float* __restrict__ out) {
    __shared__ double sd[256];
    const int tid = threadIdx.x;

    double s = 0.0;
    for (int i = tid; i < BTL_BLOCKS; i += 256) s += (double)g_btl_partial[i];
    sd[tid] = s;
    __syncthreads();
    #pragma unroll
    for (int o = 128; o > 0; o >>= 1) {
        if (tid < o) sd[tid] += sd[tid + o];
        __syncthreads();
    }
    if (tid == 0) out[0] = (float)sd[0];
    __syncthreads();

    s = 0.0;
    for (int i = tid; i < AR_BLOCKS; i += 256) s += g_ar_partial[i];
    sd[tid] = s;
    __syncthreads();
    #pragma unroll
    for (int o = 128; o > 0; o >>= 1) {
        if (tid < o) sd[tid] += sd[tid + o];
        __syncthreads();
    }
    if (tid == 0) out[1] = (float)sd[0];
}

extern "C" void kernel_launch(void* const* d_in, const int* in_sizes, int n_in,
                              void* d_out, int out_size) {
    const float* Z     = (const float*)d_in[0];
    const float* W     = (const float*)d_in[1];
    const float* Phi   = (const float*)d_in[2];
    const float* alpha = (const float*)d_in[3];
    float* out = (float*)d_out;

    phiT_kernel<<<dim3(8, 8, 4), 256>>>(Phi);
    mega_kernel<<<TOTAL_BLOCKS, 256>>>(Z, W, alpha);
    finalize_kernel<<<1, 256>>>(out);
}